// round 11
// baseline (speedup 1.0000x reference)
#include <cuda_runtime.h>
#include <cuda_fp16.h>
#include <math.h>
#include <stdint.h>

// Problem constants
#define NNODES 40000
#define NEDGES 640000
#define ETOT   (NEDGES + NNODES)   // edges + appended self loops
#define HDIM   128
#define SCAN_NB 40                 // ceil(NNODES / 1024)
#define GATH_NB 2500               // NNODES*16/256 exactly

// ---------------------------------------------------------------------------
// Scratch (device globals; no allocation allowed in kernel_launch)
// ---------------------------------------------------------------------------
__device__ __align__(16) __half g_h0[(size_t)NNODES * HDIM];  // 10.25 MB
__device__ __align__(16) __half g_h1[(size_t)NNODES * HDIM];  // 10.25 MB
__device__ int   g_csr[ETOT];            // packed: col | (invalid << 31)
__device__ int   g_cnt[NNODES];          // edge count per row (excl. self loop)
__device__ int   g_offs[NNODES + 1];
__device__ int   g_cur[NNODES];
__device__ int   g_bsum[64];
__device__ float g_dinv[NNODES];
__device__ float g_psum[(size_t)GATH_NB * HDIM];   // per-block pool partials, 1.28MB
__device__ float g_wprep[6 * 128 * 32 * 4];  // 6 tf32-interleaved Weff, 393KB
__device__ int   g_is64;

// ---------------------------------------------------------------------------
// fp16 helpers: 8 features (16 B) per lane
// ---------------------------------------------------------------------------
struct F8 { float v[8]; };
__device__ __forceinline__ F8 ldh8(const __half* p) {
    uint4 u = *(const uint4*)p;
    F8 r; float2 f;
    f = __half22float2(*(__half2*)&u.x); r.v[0] = f.x; r.v[1] = f.y;
    f = __half22float2(*(__half2*)&u.y); r.v[2] = f.x; r.v[3] = f.y;
    f = __half22float2(*(__half2*)&u.z); r.v[4] = f.x; r.v[5] = f.y;
    f = __half22float2(*(__half2*)&u.w); r.v[6] = f.x; r.v[7] = f.y;
    return r;
}
__device__ __forceinline__ void sth8(__half* p, const float* v) {
    uint4 u;
    *(__half2*)&u.x = __floats2half2_rn(v[0], v[1]);
    *(__half2*)&u.y = __floats2half2_rn(v[2], v[3]);
    *(__half2*)&u.z = __floats2half2_rn(v[4], v[5]);
    *(__half2*)&u.w = __floats2half2_rn(v[6], v[7]);
    *(uint4*)p = u;
}

// ---------------------------------------------------------------------------
// tf32 helpers
// ---------------------------------------------------------------------------
__device__ __forceinline__ uint32_t f2tf32(float v) {
    uint32_t r;
    asm("cvt.rna.tf32.f32 %0, %1;" : "=r"(r) : "f"(v));
    return r;
}
__device__ __forceinline__ int kpos8(int k) {   // k in [0,32)
    return (k >> 3) * 8 + (k & 3) * 2 + ((k >> 2) & 1);
}

// ---------------------------------------------------------------------------
// Combined prep kernel: blocks 0-5 build tf32-interleaved Weff (wprep);
// blocks 6.. zero cnt; block 6 also detects edge_index dtype (int64 vs int32).
// ---------------------------------------------------------------------------
__global__ __launch_bounds__(1024) void prep_kernel(
    const float* Wg0, const float* Wa0, const float* Wg1, const float* Wa1,
    const float* Wg2, const float* Wa2, float* wout,
    const void* ei, int* cnt)
{
    int b = blockIdx.x;
    if (b < 6) {
        const float* W; bool add;
        switch (b) {
            case 0: W = Wg0; add = false; break;
            case 1: W = Wa0; add = false; break;
            case 2: W = Wg1; add = true;  break;
            case 3: W = Wa1; add = false; break;
            case 4: W = Wg2; add = true;  break;
            default: W = Wa2; add = false; break;
        }
        for (int i = threadIdx.x; i < 128 * 128; i += blockDim.x) {
            int n = i & 127, k = i >> 7;
            float v = W[(size_t)k * 128 + n];
            if (add) v += W[(size_t)(k + 128) * 128 + n];
            int ck = k >> 5, kp = kpos8(k & 31);
            wout[(((size_t)(b * 4 + ck) * 128 + n) * 32) + kp] = __uint_as_float(f2tf32(v));
        }
        return;
    }
    int vb = b - 6;
    int i = vb * 1024 + threadIdx.x;
    if (i < NNODES) cnt[i] = 0;
    if (vb == 0) {
        __shared__ int ok;
        if (threadIdx.x == 0) ok = 1;
        __syncthreads();
        const long long* p = (const long long*)ei;
        long long v = p[threadIdx.x];      // 1024 samples
        if (v < 0 || v >= NNODES) atomicAnd(&ok, 0);
        __syncthreads();
        if (threadIdx.x == 0) g_is64 = ok;
    }
}

__global__ void cnt_acc_kernel(const void* ei, int* cnt) {
    int e = blockIdx.x * blockDim.x + threadIdx.x;
    if (e >= NEDGES) return;
    int r = g_is64 ? (int)((const long long*)ei)[e] : ((const int*)ei)[e];
    atomicAdd(&cnt[r], 1);
}

// Phase 1: per-block (1024) exclusive scan of deg = cnt+1; block totals.
__global__ __launch_bounds__(1024) void scan1_kernel(
    const int* __restrict__ cnt, int* __restrict__ excl, int* __restrict__ bsum)
{
    __shared__ int wsum[32];
    int t = threadIdx.x;
    int i = blockIdx.x * 1024 + t;
    int lane = t & 31, w = t >> 5;
    int v = (i < NNODES) ? (cnt[i] + 1) : 0;    // +1 = appended self loop
    int s = v;
#pragma unroll
    for (int d = 1; d < 32; d <<= 1) {
        int u = __shfl_up_sync(0xffffffffu, s, d);
        if (lane >= d) s += u;
    }
    if (lane == 31) wsum[w] = s;
    __syncthreads();
    if (w == 0) {
        int ws = wsum[lane];
#pragma unroll
        for (int d = 1; d < 32; d <<= 1) {
            int u = __shfl_up_sync(0xffffffffu, ws, d);
            if (lane >= d) ws += u;
        }
        wsum[lane] = ws;
    }
    __syncthreads();
    int incl = s + (w ? wsum[w - 1] : 0);
    if (i < NNODES) excl[i] = incl - v;
    if (t == 0) bsum[blockIdx.x] = wsum[31];
}

// Phase 2+3 merged: each block prefix-sums bsum locally, finalizes offsets.
__global__ __launch_bounds__(1024) void scan3_kernel(
    const int* __restrict__ cnt, const int* __restrict__ bsum,
    int* __restrict__ offs, int* __restrict__ cur, float* __restrict__ dinv)
{
    __shared__ int base;
    if (threadIdx.x == 0) {
        int run = 0;
        for (int b = 0; b < (int)blockIdx.x; b++) run += bsum[b];
        base = run;
    }
    __syncthreads();
    int i = blockIdx.x * 1024 + threadIdx.x;
    if (i < NNODES) {
        int off = offs[i] + base;
        offs[i] = off;
        cur[i]  = off;
        dinv[i] = rsqrtf((float)(cnt[i] + 1));
    }
    if (i == 0) offs[NNODES] = ETOT;
}

__global__ void csr_scatter_kernel(const void* ei, int* cur, int* csr) {
    int e = blockIdx.x * blockDim.x + threadIdx.x;
    if (e >= ETOT) return;
    int r, c, invalid = 0;
    if (e < NEDGES) {
        if (g_is64) {
            const long long* p = (const long long*)ei;
            r = (int)p[e]; c = (int)p[NEDGES + e];
        } else {
            const int* p = (const int*)ei;
            r = p[e]; c = p[NEDGES + e];
        }
        if (r == c) invalid = (int)0x80000000;  // masked for GAT, kept for GCN
    } else {
        r = c = e - NEDGES;
    }
    int pos = atomicAdd(&cur[r], 1);
    csr[pos] = c | invalid;
}

// ---------------------------------------------------------------------------
// tf32 tensor-core GEMM: C[M,128] = A[M,128] @ Weff[128,128] (+bias|rowscale).
// 256 threads (8 warps, 2 along M x 4 along N), warp tile 64x32.
// SCALE: multiply each output row by dinv[row] (folds GCN symmetric norm).
// ---------------------------------------------------------------------------
#define KS_STRIDE 40

__device__ __forceinline__ void mma_tf32(float4& c, uint32_t a0, uint32_t a1,
                                         uint32_t a2, uint32_t a3,
                                         uint32_t b0, uint32_t b1) {
    asm volatile(
        "mma.sync.aligned.m16n8k8.row.col.f32.tf32.tf32.f32 "
        "{%0,%1,%2,%3}, {%4,%5,%6,%7}, {%8,%9}, {%0,%1,%2,%3};"
        : "+f"(c.x), "+f"(c.y), "+f"(c.z), "+f"(c.w)
        : "r"(a0), "r"(a1), "r"(a2), "r"(a3), "r"(b0), "r"(b1));
}

template<bool AHALF, bool BIAS, bool SCALE>
__global__ __launch_bounds__(256) void mm_tf32_k128(
    const void* __restrict__ Av, const float* __restrict__ wprep, int mat,
    const float* __restrict__ bias, const float* __restrict__ rs,
    __half* __restrict__ C, int M)
{
    __shared__ float Wp[128 * KS_STRIDE];   // [n=128][kpos 0..31]
    __shared__ float Ap[128 * KS_STRIDE];   // [m=128][kpos 0..31]

    const int t    = threadIdx.x;
    const int warp = t >> 5;
    const int lane = t & 31;
    const int gid  = lane >> 2;             // 0..7
    const int tg   = lane & 3;              // 0..3
    const int wm   = warp & 1;              // 2 warps along M (64 rows each)
    const int wn   = warp >> 1;             // 4 warps along N (32 cols each)
    const int m0   = blockIdx.x * 128;

    float4 c[4][4];
#pragma unroll
    for (int i = 0; i < 4; i++)
#pragma unroll
        for (int j = 0; j < 4; j++) c[i][j] = make_float4(0.f, 0.f, 0.f, 0.f);

    for (int ck = 0; ck < 4; ck++) {
        __syncthreads();
        // Stage W chunk: pre-interleaved, pure float4 copies (4 iters)
        const float* wsrc = wprep + ((size_t)(mat * 4 + ck) * 128) * 32;
        for (int i = t; i < 1024; i += 256) {
            int n   = i >> 3;
            int kp4 = (i & 7) << 2;
            *(float4*)&Wp[(size_t)n * KS_STRIDE + kp4] =
                *(const float4*)&wsrc[(size_t)n * 32 + kp4];
        }
        // Stage A chunk: 512 groups of 8 consecutive k (2 iters)
        for (int i = t; i < 512; i += 256) {
            int m = i >> 2;                  // 0..127
            int g = i & 3;                   // 8-k group
            float va[8];
            if (AHALF) {
                F8 v = {};
                if (m0 + m < M)
                    v = ldh8((const __half*)Av + (size_t)(m0 + m) * 128 + ck * 32 + g * 8);
#pragma unroll
                for (int j = 0; j < 8; j++) va[j] = v.v[j];  // fp16 exact in tf32
            } else {
                float4 v0 = make_float4(0.f,0.f,0.f,0.f), v1 = v0;
                if (m0 + m < M) {
                    const float* ap = (const float*)Av + (size_t)(m0 + m) * 128 + ck * 32 + g * 8;
                    v0 = *(const float4*)ap;
                    v1 = *(const float4*)(ap + 4);
                }
                va[0] = __uint_as_float(f2tf32(v0.x)); va[1] = __uint_as_float(f2tf32(v0.y));
                va[2] = __uint_as_float(f2tf32(v0.z)); va[3] = __uint_as_float(f2tf32(v0.w));
                va[4] = __uint_as_float(f2tf32(v1.x)); va[5] = __uint_as_float(f2tf32(v1.y));
                va[6] = __uint_as_float(f2tf32(v1.z)); va[7] = __uint_as_float(f2tf32(v1.w));
            }
            float* ap = &Ap[(size_t)m * KS_STRIDE + g * 8];
#pragma unroll
            for (int j = 0; j < 4; j++)      // pair (k, k+4) -> words (2j, 2j+1)
                *(float2*)&ap[j * 2] = make_float2(va[j], va[j + 4]);
        }
        __syncthreads();

#pragma unroll
        for (int ks = 0; ks < 4; ks++) {
            const int kb = ks * 8 + tg * 2;
            uint32_t b0[4], b1[4];
#pragma unroll
            for (int nt = 0; nt < 4; nt++) {
                int col = wn * 32 + nt * 8 + gid;
                float2 b = *(const float2*)&Wp[(size_t)col * KS_STRIDE + kb];
                b0[nt] = __float_as_uint(b.x);
                b1[nt] = __float_as_uint(b.y);
            }
#pragma unroll
            for (int mt = 0; mt < 4; mt++) {
                int row = wm * 64 + mt * 16 + gid;
                float2 a02 = *(const float2*)&Ap[(size_t)row * KS_STRIDE + kb];
                float2 a13 = *(const float2*)&Ap[(size_t)(row + 8) * KS_STRIDE + kb];
                uint32_t a0 = __float_as_uint(a02.x);
                uint32_t a2 = __float_as_uint(a02.y);
                uint32_t a1 = __float_as_uint(a13.x);
                uint32_t a3 = __float_as_uint(a13.y);
#pragma unroll
                for (int nt = 0; nt < 4; nt++)
                    mma_tf32(c[mt][nt], a0, a1, a2, a3, b0[nt], b1[nt]);
            }
        }
    }

    // Epilogue: optional per-row scale (GCN norm fold) or bias; fp16 output
#pragma unroll
    for (int mt = 0; mt < 4; mt++) {
        int r0 = m0 + wm * 64 + mt * 16 + gid;
        float s0 = 1.f, s1 = 1.f;
        if (SCALE) {
            if (r0 < M)     s0 = __ldg(&rs[r0]);
            if (r0 + 8 < M) s1 = __ldg(&rs[r0 + 8]);
        }
#pragma unroll
        for (int nt = 0; nt < 4; nt++) {
            int col = wn * 32 + nt * 8 + tg * 2;
            float bx = 0.f, by = 0.f;
            if (BIAS) { bx = __ldg(&bias[col]); by = __ldg(&bias[col + 1]); }
            if (r0 < M)
                *(__half2*)&C[(size_t)r0 * 128 + col] =
                    __floats2half2_rn(c[mt][nt].x * s0 + bx, c[mt][nt].y * s0 + by);
            if (r0 + 8 < M)
                *(__half2*)&C[(size_t)(r0 + 8) * 128 + col] =
                    __floats2half2_rn(c[mt][nt].z * s1 + bx, c[mt][nt].w * s1 + by);
        }
    }
}

// ---------------------------------------------------------------------------
// GCN gather: 16 lanes per node (2 nodes/warp). Input rows PRE-SCALED by
// dinv[c]. Software-pipelined: next iteration's 4 csr indices load while
// current feature loads are in flight. out = relu(dinv_r * sum + bias).
// ---------------------------------------------------------------------------
__global__ __launch_bounds__(256) void gcn_gather_kernel(
    const __half* __restrict__ xw, const int* __restrict__ offs,
    const int* __restrict__ csr, const float* __restrict__ dinv,
    const float* __restrict__ bias, __half* __restrict__ out)
{
    int node = (blockIdx.x * 256 + threadIdx.x) >> 4;
    int co   = (threadIdx.x & 15) * 8;
    if (node >= NNODES) return;
    int s = __ldg(&offs[node]);
    int e = __ldg(&offs[node + 1]);
    float dr = __ldg(&dinv[node]);

    float a0[8] = {0,0,0,0,0,0,0,0}, a1[8] = {0,0,0,0,0,0,0,0};
    int p = s;
    int i0, i1, i2, i3;
    bool have = (p + 4 <= e);
    if (have) {
        i0 = __ldg(&csr[p + 0]); i1 = __ldg(&csr[p + 1]);
        i2 = __ldg(&csr[p + 2]); i3 = __ldg(&csr[p + 3]);
    }
    while (have) {
        int c0 = i0 & 0x7fffffff, c1 = i1 & 0x7fffffff;
        int c2 = i2 & 0x7fffffff, c3 = i3 & 0x7fffffff;
        int np = p + 4;
        bool nh = (np + 4 <= e);
        if (nh) {   // prefetch next indices; overlaps with feature loads below
            i0 = __ldg(&csr[np + 0]); i1 = __ldg(&csr[np + 1]);
            i2 = __ldg(&csr[np + 2]); i3 = __ldg(&csr[np + 3]);
        }
        F8 v0 = ldh8(xw + (size_t)c0 * 128 + co);
        F8 v1 = ldh8(xw + (size_t)c1 * 128 + co);
        F8 v2 = ldh8(xw + (size_t)c2 * 128 + co);
        F8 v3 = ldh8(xw + (size_t)c3 * 128 + co);
#pragma unroll
        for (int j = 0; j < 8; j++) {
            a0[j] += v0.v[j] + v2.v[j];
            a1[j] += v1.v[j] + v3.v[j];
        }
        p = np; have = nh;
    }
    for (; p < e; p++) {
        int c0 = __ldg(&csr[p]) & 0x7fffffff;
        F8 v0 = ldh8(xw + (size_t)c0 * 128 + co);
#pragma unroll
        for (int j = 0; j < 8; j++) a0[j] += v0.v[j];
    }
    float4 b0 = *(const float4*)&bias[co];
    float4 b1 = *(const float4*)&bias[co + 4];
    float bb[8] = {b0.x, b0.y, b0.z, b0.w, b1.x, b1.y, b1.z, b1.w};
    float r[8];
#pragma unroll
    for (int j = 0; j < 8; j++)
        r[j] = fmaxf(fmaf(a0[j] + a1[j], dr, bb[j]), 0.0f);
    sth8(out + (size_t)node * 128 + co, r);
}

// ---------------------------------------------------------------------------
// GAT gather: 16 lanes per node (2 nodes/warp), group-mask shfl reduce,
// no-max softmax (logits bounded ~+-25, fp32 exp safe). Software-pipelined
// csr index loads. LAST variant: skip feature write; block-reduce the pooled
// column sums into g_psum[block] (deterministic, no atomics).
// ---------------------------------------------------------------------------
template<bool LAST>
__global__ __launch_bounds__(256) void gat_gather_kernel(
    const __half* __restrict__ h, const int* __restrict__ offs,
    const int* __restrict__ csr, __half* __restrict__ out,
    float* __restrict__ psum)
{
    int node = (blockIdx.x * 256 + threadIdx.x) >> 4;
    int co   = (threadIdx.x & 15) * 8;
    const unsigned gmask = 0xFFFFu << (threadIdx.x & 16);   // this 16-lane group
    if (node >= NNODES) return;      // never taken (grid exact); kept for safety
    int s = __ldg(&offs[node]);
    int e = __ldg(&offs[node + 1]);

    F8 hr = ldh8(h + (size_t)node * 128 + co);

    float den = 0.0f;
    float a0[8] = {0,0,0,0,0,0,0,0}, a1[8] = {0,0,0,0,0,0,0,0};

    int p = s;
    int i0, i1, i2, i3;
    bool have = (p + 4 <= e);
    if (have) {
        i0 = __ldg(&csr[p + 0]); i1 = __ldg(&csr[p + 1]);
        i2 = __ldg(&csr[p + 2]); i3 = __ldg(&csr[p + 3]);
    }
    while (have) {
        int r0 = i0, r1 = i1, r2 = i2, r3 = i3;
        int np = p + 4;
        bool nh = (np + 4 <= e);
        if (nh) {   // prefetch next indices
            i0 = __ldg(&csr[np + 0]); i1 = __ldg(&csr[np + 1]);
            i2 = __ldg(&csr[np + 2]); i3 = __ldg(&csr[np + 3]);
        }
        F8 h0 = ldh8(h + (size_t)(r0 & 0x7fffffff) * 128 + co);
        F8 h1 = ldh8(h + (size_t)(r1 & 0x7fffffff) * 128 + co);
        F8 h2 = ldh8(h + (size_t)(r2 & 0x7fffffff) * 128 + co);
        F8 h3 = ldh8(h + (size_t)(r3 & 0x7fffffff) * 128 + co);
        float t0 = 0.f, t1 = 0.f, t2 = 0.f, t3 = 0.f;
#pragma unroll
        for (int j = 0; j < 8; j++) {
            t0 = fmaf(h0.v[j], hr.v[j], t0);
            t1 = fmaf(h1.v[j], hr.v[j], t1);
            t2 = fmaf(h2.v[j], hr.v[j], t2);
            t3 = fmaf(h3.v[j], hr.v[j], t3);
        }
#pragma unroll
        for (int sh = 8; sh; sh >>= 1) {
            t0 += __shfl_xor_sync(gmask, t0, sh);
            t1 += __shfl_xor_sync(gmask, t1, sh);
            t2 += __shfl_xor_sync(gmask, t2, sh);
            t3 += __shfl_xor_sync(gmask, t3, sh);
        }
        float w0 = (r0 >= 0) ? __expf((t0 >= 0.f) ? t0 : 0.2f * t0) : 0.f;
        float w1 = (r1 >= 0) ? __expf((t1 >= 0.f) ? t1 : 0.2f * t1) : 0.f;
        float w2 = (r2 >= 0) ? __expf((t2 >= 0.f) ? t2 : 0.2f * t2) : 0.f;
        float w3 = (r3 >= 0) ? __expf((t3 >= 0.f) ? t3 : 0.2f * t3) : 0.f;
        den += (w0 + w1) + (w2 + w3);
#pragma unroll
        for (int j = 0; j < 8; j++) {
            a0[j] = fmaf(h0.v[j], w0, fmaf(h2.v[j], w2, a0[j]));
            a1[j] = fmaf(h1.v[j], w1, fmaf(h3.v[j], w3, a1[j]));
        }
        p = np; have = nh;
    }
    for (; p < e; p++) {
        int r0 = __ldg(&csr[p]);
        F8 h0 = ldh8(h + (size_t)(r0 & 0x7fffffff) * 128 + co);
        float t0 = 0.f;
#pragma unroll
        for (int j = 0; j < 8; j++) t0 = fmaf(h0.v[j], hr.v[j], t0);
#pragma unroll
        for (int sh = 8; sh; sh >>= 1) t0 += __shfl_xor_sync(gmask, t0, sh);
        float w0 = (r0 >= 0) ? __expf((t0 >= 0.f) ? t0 : 0.2f * t0) : 0.f;
        den += w0;
#pragma unroll
        for (int j = 0; j < 8; j++) a0[j] = fmaf(h0.v[j], w0, a0[j]);
    }

    float inv = 1.0f / fmaxf(den, 1e-16f);   // den >= exp(self-loop) > 0
    float r[8];
#pragma unroll
    for (int j = 0; j < 8; j++) r[j] = (a0[j] + a1[j]) * inv;

    if (!LAST) {
        sth8(out + (size_t)node * 128 + co, r);
    } else {
        // Fused global-mean-pool partial: block-reduce 256 node-halves.
        __shared__ float sm[16][HDIM];
        int rg = threadIdx.x >> 4;           // 0..15
#pragma unroll
        for (int j = 0; j < 8; j++) sm[rg][co + j] = r[j];
        __syncthreads();
        int t = threadIdx.x;
        if (t < HDIM) {
            float tot = 0.f;
#pragma unroll
            for (int g = 0; g < 16; g++) tot += sm[g][t];
            psum[(size_t)blockIdx.x * HDIM + t] = tot;
        }
    }
}

// ---------------------------------------------------------------------------
// Final writeout: reduce GATH_NB per-block pool partials -> d_out (x2 concat).
// ---------------------------------------------------------------------------
__global__ __launch_bounds__(128) void writeout_kernel(
    const float* __restrict__ psum, float* __restrict__ out)
{
    int t = threadIdx.x;                     // 128 threads, one per column
    float s0 = 0.f, s1 = 0.f, s2 = 0.f, s3 = 0.f;
    int b = 0;
    for (; b + 4 <= GATH_NB; b += 4) {
        s0 += psum[(size_t)(b + 0) * HDIM + t];
        s1 += psum[(size_t)(b + 1) * HDIM + t];
        s2 += psum[(size_t)(b + 2) * HDIM + t];
        s3 += psum[(size_t)(b + 3) * HDIM + t];
    }
    for (; b < GATH_NB; b++) s0 += psum[(size_t)b * HDIM + t];
    float v = ((s0 + s1) + (s2 + s3)) * (1.0f / (float)NNODES);
    out[t] = v;
    out[t + HDIM] = v;                       // concat([h,h]) halves identical
}

// ---------------------------------------------------------------------------
// Launch
// ---------------------------------------------------------------------------
extern "C" void kernel_launch(void* const* d_in, const int* in_sizes, int n_in,
                              void* d_out, int out_size)
{
    const float* x  = (const float*)d_in[0];
    const void*  ei = d_in[1];
    const float* Wg[3] = {(const float*)d_in[2], (const float*)d_in[6],  (const float*)d_in[10]};
    const float* bg[3] = {(const float*)d_in[3], (const float*)d_in[7],  (const float*)d_in[11]};
    const float* Wa[3] = {(const float*)d_in[4], (const float*)d_in[8],  (const float*)d_in[12]};
    const float* ba[3] = {(const float*)d_in[5], (const float*)d_in[9],  (const float*)d_in[13]};

    __half *h0, *h1;
    float *dinv, *psum, *wprep;
    int *csr, *cnt, *offs, *cur, *bsum;
    cudaGetSymbolAddress((void**)&h0,   g_h0);
    cudaGetSymbolAddress((void**)&h1,   g_h1);
    cudaGetSymbolAddress((void**)&dinv, g_dinv);
    cudaGetSymbolAddress((void**)&psum, g_psum);
    cudaGetSymbolAddress((void**)&wprep,g_wprep);
    cudaGetSymbolAddress((void**)&csr,  g_csr);
    cudaGetSymbolAddress((void**)&cnt,  g_cnt);
    cudaGetSymbolAddress((void**)&offs, g_offs);
    cudaGetSymbolAddress((void**)&cur,  g_cur);
    cudaGetSymbolAddress((void**)&bsum, g_bsum);

    const int NB_E    = (NEDGES + 255) / 256;
    const int NB_ET   = (ETOT + 255) / 256;
    const int NB_GEMM = (NNODES + 127) / 128;        // 313

    // Combined weight prep + cnt zero + dtype detect
    prep_kernel<<<6 + SCAN_NB, 1024>>>(Wg[0], Wa[0], Wg[1], Wa[1], Wg[2], Wa[2],
                                       wprep, ei, cnt);
    cnt_acc_kernel<<<NB_E, 256>>>(ei, cnt);
    scan1_kernel<<<SCAN_NB, 1024>>>(cnt, offs, bsum);
    scan3_kernel<<<SCAN_NB, 1024>>>(cnt, bsum, offs, cur, dinv);
    csr_scatter_kernel<<<NB_ET, 256>>>(ei, cur, csr);

    for (int l = 0; l < 3; l++) {
        // --- GCN: GEMM(row-scale by dinv) -> sum-gather(+bias+relu) ---
        if (l == 0)
            mm_tf32_k128<false, false, true><<<NB_GEMM, 256>>>(x,  wprep, 0,     nullptr, dinv, h0, NNODES);
        else
            mm_tf32_k128<true,  false, true><<<NB_GEMM, 256>>>(h1, wprep, l * 2, nullptr, dinv, h0, NNODES);
        gcn_gather_kernel<<<GATH_NB, 256>>>(h0, offs, csr, dinv, bg[l], h1);

        // --- GAT: GEMM(+bias) -> fused softmax gather ---
        mm_tf32_k128<true, true, false><<<NB_GEMM, 256>>>(h1, wprep, l * 2 + 1, ba[l], nullptr, h0, NNODES);
        if (l < 2)
            gat_gather_kernel<false><<<GATH_NB, 256>>>(h0, offs, csr, h1, nullptr);
        else
            gat_gather_kernel<true><<<GATH_NB, 256>>>(h0, offs, csr, nullptr, psum);
    }

    // Reduce pool partials -> output
    writeout_kernel<<<1, 128>>>(psum, (float*)d_out);
}

// round 12
// speedup vs baseline: 1.0125x; 1.0125x over previous
#include <cuda_runtime.h>
#include <cuda_fp16.h>
#include <math.h>
#include <stdint.h>

// Problem constants
#define NNODES 40000
#define NEDGES 640000
#define ETOT   (NEDGES + NNODES)   // edges + appended self loops
#define HDIM   128
#define SCAN_NB 40                 // ceil(NNODES / 1024)
#define GATH_NB 2500               // NNODES*16/256 exactly

// ---------------------------------------------------------------------------
// Scratch (device globals; no allocation allowed in kernel_launch)
// ---------------------------------------------------------------------------
__device__ __align__(16) __half g_h0[(size_t)NNODES * HDIM];  // 10.25 MB
__device__ __align__(16) __half g_h1[(size_t)NNODES * HDIM];  // 10.25 MB
__device__ int   g_csr[ETOT];            // packed: col | (invalid << 31)
__device__ int   g_cnt[NNODES];          // edge count per row (excl. self loop)
__device__ int   g_offs[NNODES + 1];
__device__ int   g_cur[NNODES];
__device__ int   g_bsum[64];
__device__ float g_dinv[NNODES];
__device__ float g_psum[(size_t)GATH_NB * HDIM];   // per-block pool partials
__device__ float g_wprep[6 * 128 * 32 * 4];  // 6 tf32-interleaved Weff, 393KB
__device__ int   g_is64;

// ---------------------------------------------------------------------------
// fp16 helpers: 8 features (16 B) per lane
// ---------------------------------------------------------------------------
struct F8 { float v[8]; };
__device__ __forceinline__ F8 ldh8(const __half* p) {
    uint4 u = *(const uint4*)p;
    F8 r; float2 f;
    f = __half22float2(*(__half2*)&u.x); r.v[0] = f.x; r.v[1] = f.y;
    f = __half22float2(*(__half2*)&u.y); r.v[2] = f.x; r.v[3] = f.y;
    f = __half22float2(*(__half2*)&u.z); r.v[4] = f.x; r.v[5] = f.y;
    f = __half22float2(*(__half2*)&u.w); r.v[6] = f.x; r.v[7] = f.y;
    return r;
}
__device__ __forceinline__ void sth8(__half* p, const float* v) {
    uint4 u;
    *(__half2*)&u.x = __floats2half2_rn(v[0], v[1]);
    *(__half2*)&u.y = __floats2half2_rn(v[2], v[3]);
    *(__half2*)&u.z = __floats2half2_rn(v[4], v[5]);
    *(__half2*)&u.w = __floats2half2_rn(v[6], v[7]);
    *(uint4*)p = u;
}

// ---------------------------------------------------------------------------
// tf32 helpers
// ---------------------------------------------------------------------------
__device__ __forceinline__ uint32_t f2tf32(float v) {
    uint32_t r;
    asm("cvt.rna.tf32.f32 %0, %1;" : "=r"(r) : "f"(v));
    return r;
}
__device__ __forceinline__ int kpos8(int k) {   // k in [0,32)
    return (k >> 3) * 8 + (k & 3) * 2 + ((k >> 2) & 1);
}

// ---------------------------------------------------------------------------
// Combined prep kernel: blocks 0-5 build tf32-interleaved Weff (wprep);
// blocks 6.. zero cnt; block 6 also detects edge_index dtype (int64 vs int32).
// ---------------------------------------------------------------------------
__global__ __launch_bounds__(1024) void prep_kernel(
    const float* Wg0, const float* Wa0, const float* Wg1, const float* Wa1,
    const float* Wg2, const float* Wa2, float* wout,
    const void* ei, int* cnt)
{
    int b = blockIdx.x;
    if (b < 6) {
        const float* W; bool add;
        switch (b) {
            case 0: W = Wg0; add = false; break;
            case 1: W = Wa0; add = false; break;
            case 2: W = Wg1; add = true;  break;
            case 3: W = Wa1; add = false; break;
            case 4: W = Wg2; add = true;  break;
            default: W = Wa2; add = false; break;
        }
        for (int i = threadIdx.x; i < 128 * 128; i += blockDim.x) {
            int n = i & 127, k = i >> 7;
            float v = W[(size_t)k * 128 + n];
            if (add) v += W[(size_t)(k + 128) * 128 + n];
            int ck = k >> 5, kp = kpos8(k & 31);
            wout[(((size_t)(b * 4 + ck) * 128 + n) * 32) + kp] = __uint_as_float(f2tf32(v));
        }
        return;
    }
    int vb = b - 6;
    int i = vb * 1024 + threadIdx.x;
    if (i < NNODES) cnt[i] = 0;
    if (vb == 0) {
        __shared__ int ok;
        if (threadIdx.x == 0) ok = 1;
        __syncthreads();
        const long long* p = (const long long*)ei;
        long long v = p[threadIdx.x];      // 1024 samples
        if (v < 0 || v >= NNODES) atomicAnd(&ok, 0);
        __syncthreads();
        if (threadIdx.x == 0) g_is64 = ok;
    }
}

__global__ void cnt_acc_kernel(const void* ei, int* cnt) {
    int e = blockIdx.x * blockDim.x + threadIdx.x;
    if (e >= NEDGES) return;
    int r = g_is64 ? (int)((const long long*)ei)[e] : ((const int*)ei)[e];
    atomicAdd(&cnt[r], 1);
}

// Phase 1: per-block (1024) exclusive scan of deg = cnt+1; block totals.
__global__ __launch_bounds__(1024) void scan1_kernel(
    const int* __restrict__ cnt, int* __restrict__ excl, int* __restrict__ bsum)
{
    __shared__ int wsum[32];
    int t = threadIdx.x;
    int i = blockIdx.x * 1024 + t;
    int lane = t & 31, w = t >> 5;
    int v = (i < NNODES) ? (cnt[i] + 1) : 0;    // +1 = appended self loop
    int s = v;
#pragma unroll
    for (int d = 1; d < 32; d <<= 1) {
        int u = __shfl_up_sync(0xffffffffu, s, d);
        if (lane >= d) s += u;
    }
    if (lane == 31) wsum[w] = s;
    __syncthreads();
    if (w == 0) {
        int ws = wsum[lane];
#pragma unroll
        for (int d = 1; d < 32; d <<= 1) {
            int u = __shfl_up_sync(0xffffffffu, ws, d);
            if (lane >= d) ws += u;
        }
        wsum[lane] = ws;
    }
    __syncthreads();
    int incl = s + (w ? wsum[w - 1] : 0);
    if (i < NNODES) excl[i] = incl - v;
    if (t == 0) bsum[blockIdx.x] = wsum[31];
}

// Phase 2+3 merged: each block prefix-sums bsum locally, finalizes offsets.
__global__ __launch_bounds__(1024) void scan3_kernel(
    const int* __restrict__ cnt, const int* __restrict__ bsum,
    int* __restrict__ offs, int* __restrict__ cur, float* __restrict__ dinv)
{
    __shared__ int base;
    if (threadIdx.x == 0) {
        int run = 0;
        for (int b = 0; b < (int)blockIdx.x; b++) run += bsum[b];
        base = run;
    }
    __syncthreads();
    int i = blockIdx.x * 1024 + threadIdx.x;
    if (i < NNODES) {
        int off = offs[i] + base;
        offs[i] = off;
        cur[i]  = off;
        dinv[i] = rsqrtf((float)(cnt[i] + 1));
    }
    if (i == 0) offs[NNODES] = ETOT;
}

__global__ void csr_scatter_kernel(const void* ei, int* cur, int* csr) {
    int e = blockIdx.x * blockDim.x + threadIdx.x;
    if (e >= ETOT) return;
    int r, c, invalid = 0;
    if (e < NEDGES) {
        if (g_is64) {
            const long long* p = (const long long*)ei;
            r = (int)p[e]; c = (int)p[NEDGES + e];
        } else {
            const int* p = (const int*)ei;
            r = p[e]; c = p[NEDGES + e];
        }
        if (r == c) invalid = (int)0x80000000;  // masked for GAT, kept for GCN
    } else {
        r = c = e - NEDGES;
    }
    int pos = atomicAdd(&cur[r], 1);
    csr[pos] = c | invalid;
}

// ---------------------------------------------------------------------------
// tf32 tensor-core GEMM: C[M,128] = A[M,128] @ Weff[128,128] (+bias|rowscale).
// 256 threads (8 warps, 2 along M x 4 along N), warp tile 64x32.
// SCALE: multiply each output row by dinv[row] (folds GCN symmetric norm).
// ---------------------------------------------------------------------------
#define KS_STRIDE 40

__device__ __forceinline__ void mma_tf32(float4& c, uint32_t a0, uint32_t a1,
                                         uint32_t a2, uint32_t a3,
                                         uint32_t b0, uint32_t b1) {
    asm volatile(
        "mma.sync.aligned.m16n8k8.row.col.f32.tf32.tf32.f32 "
        "{%0,%1,%2,%3}, {%4,%5,%6,%7}, {%8,%9}, {%0,%1,%2,%3};"
        : "+f"(c.x), "+f"(c.y), "+f"(c.z), "+f"(c.w)
        : "r"(a0), "r"(a1), "r"(a2), "r"(a3), "r"(b0), "r"(b1));
}

template<bool AHALF, bool BIAS, bool SCALE>
__global__ __launch_bounds__(256) void mm_tf32_k128(
    const void* __restrict__ Av, const float* __restrict__ wprep, int mat,
    const float* __restrict__ bias, const float* __restrict__ rs,
    __half* __restrict__ C, int M)
{
    __shared__ float Wp[128 * KS_STRIDE];   // [n=128][kpos 0..31]
    __shared__ float Ap[128 * KS_STRIDE];   // [m=128][kpos 0..31]

    const int t    = threadIdx.x;
    const int warp = t >> 5;
    const int lane = t & 31;
    const int gid  = lane >> 2;             // 0..7
    const int tg   = lane & 3;              // 0..3
    const int wm   = warp & 1;              // 2 warps along M (64 rows each)
    const int wn   = warp >> 1;             // 4 warps along N (32 cols each)
    const int m0   = blockIdx.x * 128;

    float4 c[4][4];
#pragma unroll
    for (int i = 0; i < 4; i++)
#pragma unroll
        for (int j = 0; j < 4; j++) c[i][j] = make_float4(0.f, 0.f, 0.f, 0.f);

    for (int ck = 0; ck < 4; ck++) {
        __syncthreads();
        // Stage W chunk: pre-interleaved, pure float4 copies (4 iters)
        const float* wsrc = wprep + ((size_t)(mat * 4 + ck) * 128) * 32;
        for (int i = t; i < 1024; i += 256) {
            int n   = i >> 3;
            int kp4 = (i & 7) << 2;
            *(float4*)&Wp[(size_t)n * KS_STRIDE + kp4] =
                *(const float4*)&wsrc[(size_t)n * 32 + kp4];
        }
        // Stage A chunk: 512 groups of 8 consecutive k (2 iters)
        for (int i = t; i < 512; i += 256) {
            int m = i >> 2;                  // 0..127
            int g = i & 3;                   // 8-k group
            float va[8];
            if (AHALF) {
                F8 v = {};
                if (m0 + m < M)
                    v = ldh8((const __half*)Av + (size_t)(m0 + m) * 128 + ck * 32 + g * 8);
#pragma unroll
                for (int j = 0; j < 8; j++) va[j] = v.v[j];  // fp16 exact in tf32
            } else {
                float4 v0 = make_float4(0.f,0.f,0.f,0.f), v1 = v0;
                if (m0 + m < M) {
                    const float* ap = (const float*)Av + (size_t)(m0 + m) * 128 + ck * 32 + g * 8;
                    v0 = *(const float4*)ap;
                    v1 = *(const float4*)(ap + 4);
                }
                va[0] = __uint_as_float(f2tf32(v0.x)); va[1] = __uint_as_float(f2tf32(v0.y));
                va[2] = __uint_as_float(f2tf32(v0.z)); va[3] = __uint_as_float(f2tf32(v0.w));
                va[4] = __uint_as_float(f2tf32(v1.x)); va[5] = __uint_as_float(f2tf32(v1.y));
                va[6] = __uint_as_float(f2tf32(v1.z)); va[7] = __uint_as_float(f2tf32(v1.w));
            }
            float* ap = &Ap[(size_t)m * KS_STRIDE + g * 8];
#pragma unroll
            for (int j = 0; j < 4; j++)      // pair (k, k+4) -> words (2j, 2j+1)
                *(float2*)&ap[j * 2] = make_float2(va[j], va[j + 4]);
        }
        __syncthreads();

#pragma unroll
        for (int ks = 0; ks < 4; ks++) {
            const int kb = ks * 8 + tg * 2;
            uint32_t b0[4], b1[4];
#pragma unroll
            for (int nt = 0; nt < 4; nt++) {
                int col = wn * 32 + nt * 8 + gid;
                float2 b = *(const float2*)&Wp[(size_t)col * KS_STRIDE + kb];
                b0[nt] = __float_as_uint(b.x);
                b1[nt] = __float_as_uint(b.y);
            }
#pragma unroll
            for (int mt = 0; mt < 4; mt++) {
                int row = wm * 64 + mt * 16 + gid;
                float2 a02 = *(const float2*)&Ap[(size_t)row * KS_STRIDE + kb];
                float2 a13 = *(const float2*)&Ap[(size_t)(row + 8) * KS_STRIDE + kb];
                uint32_t a0 = __float_as_uint(a02.x);
                uint32_t a2 = __float_as_uint(a02.y);
                uint32_t a1 = __float_as_uint(a13.x);
                uint32_t a3 = __float_as_uint(a13.y);
#pragma unroll
                for (int nt = 0; nt < 4; nt++)
                    mma_tf32(c[mt][nt], a0, a1, a2, a3, b0[nt], b1[nt]);
            }
        }
    }

    // Epilogue: optional per-row scale (GCN norm fold) or bias; fp16 output
#pragma unroll
    for (int mt = 0; mt < 4; mt++) {
        int r0 = m0 + wm * 64 + mt * 16 + gid;
        float s0 = 1.f, s1 = 1.f;
        if (SCALE) {
            if (r0 < M)     s0 = __ldg(&rs[r0]);
            if (r0 + 8 < M) s1 = __ldg(&rs[r0 + 8]);
        }
#pragma unroll
        for (int nt = 0; nt < 4; nt++) {
            int col = wn * 32 + nt * 8 + tg * 2;
            float bx = 0.f, by = 0.f;
            if (BIAS) { bx = __ldg(&bias[col]); by = __ldg(&bias[col + 1]); }
            if (r0 < M)
                *(__half2*)&C[(size_t)r0 * 128 + col] =
                    __floats2half2_rn(c[mt][nt].x * s0 + bx, c[mt][nt].y * s0 + by);
            if (r0 + 8 < M)
                *(__half2*)&C[(size_t)(r0 + 8) * 128 + col] =
                    __floats2half2_rn(c[mt][nt].z * s1 + bx, c[mt][nt].w * s1 + by);
        }
    }
}

// ---------------------------------------------------------------------------
// GCN gather: 16 lanes per node (2 nodes/warp). Input rows PRE-SCALED by
// dinv[c] (GEMM epilogue): pure sum of neighbor rows, unroll-4 for loop
// (round-10 structure — manual SW pipelining measured as a regression).
// out = relu(dinv_r * sum + bias).
// ---------------------------------------------------------------------------
__global__ __launch_bounds__(256) void gcn_gather_kernel(
    const __half* __restrict__ xw, const int* __restrict__ offs,
    const int* __restrict__ csr, const float* __restrict__ dinv,
    const float* __restrict__ bias, __half* __restrict__ out)
{
    int node = (blockIdx.x * 256 + threadIdx.x) >> 4;
    int co   = (threadIdx.x & 15) * 8;
    if (node >= NNODES) return;
    int s = __ldg(&offs[node]);
    int e = __ldg(&offs[node + 1]);
    float dr = __ldg(&dinv[node]);

    float a0[8] = {0,0,0,0,0,0,0,0}, a1[8] = {0,0,0,0,0,0,0,0};
    int p = s;
    for (; p + 4 <= e; p += 4) {
        int c0 = __ldg(&csr[p + 0]) & 0x7fffffff;
        int c1 = __ldg(&csr[p + 1]) & 0x7fffffff;
        int c2 = __ldg(&csr[p + 2]) & 0x7fffffff;
        int c3 = __ldg(&csr[p + 3]) & 0x7fffffff;
        F8 v0 = ldh8(xw + (size_t)c0 * 128 + co);
        F8 v1 = ldh8(xw + (size_t)c1 * 128 + co);
        F8 v2 = ldh8(xw + (size_t)c2 * 128 + co);
        F8 v3 = ldh8(xw + (size_t)c3 * 128 + co);
#pragma unroll
        for (int j = 0; j < 8; j++) {
            a0[j] += v0.v[j] + v2.v[j];
            a1[j] += v1.v[j] + v3.v[j];
        }
    }
    for (; p < e; p++) {
        int c0 = __ldg(&csr[p]) & 0x7fffffff;
        F8 v0 = ldh8(xw + (size_t)c0 * 128 + co);
#pragma unroll
        for (int j = 0; j < 8; j++) a0[j] += v0.v[j];
    }
    float4 b0 = *(const float4*)&bias[co];
    float4 b1 = *(const float4*)&bias[co + 4];
    float bb[8] = {b0.x, b0.y, b0.z, b0.w, b1.x, b1.y, b1.z, b1.w};
    float r[8];
#pragma unroll
    for (int j = 0; j < 8; j++)
        r[j] = fmaxf(fmaf(a0[j] + a1[j], dr, bb[j]), 0.0f);
    sth8(out + (size_t)node * 128 + co, r);
}

// ---------------------------------------------------------------------------
// GAT gather: 16 lanes per node (2 nodes/warp), group-mask shfl reduce,
// no-max softmax (logits bounded ~+-25, fp32 exp safe). Unroll-4 for loop
// (round-10 structure). LAST variant: skip feature write; block-reduce the
// pooled column sums into g_psum[block] (deterministic, no atomics).
// ---------------------------------------------------------------------------
template<bool LAST>
__global__ __launch_bounds__(256) void gat_gather_kernel(
    const __half* __restrict__ h, const int* __restrict__ offs,
    const int* __restrict__ csr, __half* __restrict__ out,
    float* __restrict__ psum)
{
    int node = (blockIdx.x * 256 + threadIdx.x) >> 4;
    int co   = (threadIdx.x & 15) * 8;
    const unsigned gmask = 0xFFFFu << (threadIdx.x & 16);   // this 16-lane group
    if (node >= NNODES) return;      // never taken (grid exact)
    int s = __ldg(&offs[node]);
    int e = __ldg(&offs[node + 1]);

    F8 hr = ldh8(h + (size_t)node * 128 + co);

    float den = 0.0f;
    float a0[8] = {0,0,0,0,0,0,0,0}, a1[8] = {0,0,0,0,0,0,0,0};

    int p = s;
    for (; p + 4 <= e; p += 4) {
        int r0 = __ldg(&csr[p + 0]);
        int r1 = __ldg(&csr[p + 1]);
        int r2 = __ldg(&csr[p + 2]);
        int r3 = __ldg(&csr[p + 3]);
        F8 h0 = ldh8(h + (size_t)(r0 & 0x7fffffff) * 128 + co);
        F8 h1 = ldh8(h + (size_t)(r1 & 0x7fffffff) * 128 + co);
        F8 h2 = ldh8(h + (size_t)(r2 & 0x7fffffff) * 128 + co);
        F8 h3 = ldh8(h + (size_t)(r3 & 0x7fffffff) * 128 + co);
        float t0 = 0.f, t1 = 0.f, t2 = 0.f, t3 = 0.f;
#pragma unroll
        for (int j = 0; j < 8; j++) {
            t0 = fmaf(h0.v[j], hr.v[j], t0);
            t1 = fmaf(h1.v[j], hr.v[j], t1);
            t2 = fmaf(h2.v[j], hr.v[j], t2);
            t3 = fmaf(h3.v[j], hr.v[j], t3);
        }
#pragma unroll
        for (int sh = 8; sh; sh >>= 1) {
            t0 += __shfl_xor_sync(gmask, t0, sh);
            t1 += __shfl_xor_sync(gmask, t1, sh);
            t2 += __shfl_xor_sync(gmask, t2, sh);
            t3 += __shfl_xor_sync(gmask, t3, sh);
        }
        float w0 = (r0 >= 0) ? __expf((t0 >= 0.f) ? t0 : 0.2f * t0) : 0.f;
        float w1 = (r1 >= 0) ? __expf((t1 >= 0.f) ? t1 : 0.2f * t1) : 0.f;
        float w2 = (r2 >= 0) ? __expf((t2 >= 0.f) ? t2 : 0.2f * t2) : 0.f;
        float w3 = (r3 >= 0) ? __expf((t3 >= 0.f) ? t3 : 0.2f * t3) : 0.f;
        den += (w0 + w1) + (w2 + w3);
#pragma unroll
        for (int j = 0; j < 8; j++) {
            a0[j] = fmaf(h0.v[j], w0, fmaf(h2.v[j], w2, a0[j]));
            a1[j] = fmaf(h1.v[j], w1, fmaf(h3.v[j], w3, a1[j]));
        }
    }
    for (; p < e; p++) {
        int r0 = __ldg(&csr[p]);
        F8 h0 = ldh8(h + (size_t)(r0 & 0x7fffffff) * 128 + co);
        float t0 = 0.f;
#pragma unroll
        for (int j = 0; j < 8; j++) t0 = fmaf(h0.v[j], hr.v[j], t0);
#pragma unroll
        for (int sh = 8; sh; sh >>= 1) t0 += __shfl_xor_sync(gmask, t0, sh);
        float w0 = (r0 >= 0) ? __expf((t0 >= 0.f) ? t0 : 0.2f * t0) : 0.f;
        den += w0;
#pragma unroll
        for (int j = 0; j < 8; j++) a0[j] = fmaf(h0.v[j], w0, a0[j]);
    }

    float inv = 1.0f / fmaxf(den, 1e-16f);   // den >= exp(self-loop) > 0
    float r[8];
#pragma unroll
    for (int j = 0; j < 8; j++) r[j] = (a0[j] + a1[j]) * inv;

    if (!LAST) {
        sth8(out + (size_t)node * 128 + co, r);
    } else {
        // Fused global-mean-pool partial: block-reduce the 16 nodes.
        __shared__ float sm[16][HDIM];
        int rg = threadIdx.x >> 4;           // node within block
#pragma unroll
        for (int j = 0; j < 8; j++) sm[rg][co + j] = r[j];
        __syncthreads();
        int t = threadIdx.x;
        if (t < HDIM) {
            float tot = 0.f;
#pragma unroll
            for (int g = 0; g < 16; g++) tot += sm[g][t];
            psum[(size_t)blockIdx.x * HDIM + t] = tot;
        }
    }
}

// ---------------------------------------------------------------------------
// Final writeout: reduce GATH_NB per-block pool partials -> d_out (x2 concat).
// ---------------------------------------------------------------------------
__global__ __launch_bounds__(128) void writeout_kernel(
    const float* __restrict__ psum, float* __restrict__ out)
{
    int t = threadIdx.x;                     // 128 threads, one per column
    float s0 = 0.f, s1 = 0.f, s2 = 0.f, s3 = 0.f;
    int b = 0;
    for (; b + 4 <= GATH_NB; b += 4) {
        s0 += psum[(size_t)(b + 0) * HDIM + t];
        s1 += psum[(size_t)(b + 1) * HDIM + t];
        s2 += psum[(size_t)(b + 2) * HDIM + t];
        s3 += psum[(size_t)(b + 3) * HDIM + t];
    }
    for (; b < GATH_NB; b++) s0 += psum[(size_t)b * HDIM + t];
    float v = ((s0 + s1) + (s2 + s3)) * (1.0f / (float)NNODES);
    out[t] = v;
    out[t + HDIM] = v;                       // concat([h,h]) halves identical
}

// ---------------------------------------------------------------------------
// Launch
// ---------------------------------------------------------------------------
extern "C" void kernel_launch(void* const* d_in, const int* in_sizes, int n_in,
                              void* d_out, int out_size)
{
    const float* x  = (const float*)d_in[0];
    const void*  ei = d_in[1];
    const float* Wg[3] = {(const float*)d_in[2], (const float*)d_in[6],  (const float*)d_in[10]};
    const float* bg[3] = {(const float*)d_in[3], (const float*)d_in[7],  (const float*)d_in[11]};
    const float* Wa[3] = {(const float*)d_in[4], (const float*)d_in[8],  (const float*)d_in[12]};
    const float* ba[3] = {(const float*)d_in[5], (const float*)d_in[9],  (const float*)d_in[13]};

    __half *h0, *h1;
    float *dinv, *psum, *wprep;
    int *csr, *cnt, *offs, *cur, *bsum;
    cudaGetSymbolAddress((void**)&h0,   g_h0);
    cudaGetSymbolAddress((void**)&h1,   g_h1);
    cudaGetSymbolAddress((void**)&dinv, g_dinv);
    cudaGetSymbolAddress((void**)&psum, g_psum);
    cudaGetSymbolAddress((void**)&wprep,g_wprep);
    cudaGetSymbolAddress((void**)&csr,  g_csr);
    cudaGetSymbolAddress((void**)&cnt,  g_cnt);
    cudaGetSymbolAddress((void**)&offs, g_offs);
    cudaGetSymbolAddress((void**)&cur,  g_cur);
    cudaGetSymbolAddress((void**)&bsum, g_bsum);

    const int NB_E    = (NEDGES + 255) / 256;
    const int NB_ET   = (ETOT + 255) / 256;
    const int NB_GEMM = (NNODES + 127) / 128;        // 313

    // Combined weight prep + cnt zero + dtype detect
    prep_kernel<<<6 + SCAN_NB, 1024>>>(Wg[0], Wa[0], Wg[1], Wa[1], Wg[2], Wa[2],
                                       wprep, ei, cnt);
    cnt_acc_kernel<<<NB_E, 256>>>(ei, cnt);
    scan1_kernel<<<SCAN_NB, 1024>>>(cnt, offs, bsum);
    scan3_kernel<<<SCAN_NB, 1024>>>(cnt, bsum, offs, cur, dinv);
    csr_scatter_kernel<<<NB_ET, 256>>>(ei, cur, csr);

    for (int l = 0; l < 3; l++) {
        // --- GCN: GEMM(row-scale by dinv) -> sum-gather(+bias+relu) ---
        if (l == 0)
            mm_tf32_k128<false, false, true><<<NB_GEMM, 256>>>(x,  wprep, 0,     nullptr, dinv, h0, NNODES);
        else
            mm_tf32_k128<true,  false, true><<<NB_GEMM, 256>>>(h1, wprep, l * 2, nullptr, dinv, h0, NNODES);
        gcn_gather_kernel<<<GATH_NB, 256>>>(h0, offs, csr, dinv, bg[l], h1);

        // --- GAT: GEMM(+bias) -> fused softmax gather ---
        mm_tf32_k128<true, true, false><<<NB_GEMM, 256>>>(h1, wprep, l * 2 + 1, ba[l], nullptr, h0, NNODES);
        if (l < 2)
            gat_gather_kernel<false><<<GATH_NB, 256>>>(h0, offs, csr, h1, nullptr);
        else
            gat_gather_kernel<true><<<GATH_NB, 256>>>(h0, offs, csr, nullptr, psum);
    }

    // Reduce pool partials -> output
    writeout_kernel<<<1, 128>>>(psum, (float*)d_out);
}

// round 13
// speedup vs baseline: 1.1567x; 1.1424x over previous
#include <cuda_runtime.h>
#include <cuda_fp16.h>
#include <math.h>
#include <stdint.h>

// Problem constants
#define NNODES 40000
#define NEDGES 640000
#define ETOT   (NEDGES + NNODES)   // edges + appended self loops
#define HDIM   128
#define SCAN_NB 40                 // ceil(NNODES / 1024)
#define GATH_NB 2500               // NNODES*16/256 exactly

// ---------------------------------------------------------------------------
// Scratch (device globals; no allocation allowed in kernel_launch)
// ---------------------------------------------------------------------------
__device__ __align__(16) __half g_h0[(size_t)NNODES * HDIM];  // 10.25 MB
__device__ __align__(16) __half g_h1[(size_t)NNODES * HDIM];  // 10.25 MB
__device__ int   g_csr[ETOT];            // packed: col | (invalid << 31)
__device__ int   g_cnt[NNODES];          // edge count per row (excl. self loop)
__device__ int   g_offs[NNODES + 1];
__device__ int   g_cur[NNODES];
__device__ int   g_bsum[64];
__device__ float g_dinv[NNODES];
__device__ float g_acc[HDIM];            // pooled column sums (atomic)
__device__ float g_wprep[6 * 128 * 32 * 4];  // 6 tf32-interleaved Weff, 393KB
__device__ int   g_is64;

// ---------------------------------------------------------------------------
// fp16 helpers: 8 features (16 B) per lane
// ---------------------------------------------------------------------------
struct F8 { float v[8]; };
__device__ __forceinline__ F8 ldh8(const __half* p) {
    uint4 u = *(const uint4*)p;
    F8 r; float2 f;
    f = __half22float2(*(__half2*)&u.x); r.v[0] = f.x; r.v[1] = f.y;
    f = __half22float2(*(__half2*)&u.y); r.v[2] = f.x; r.v[3] = f.y;
    f = __half22float2(*(__half2*)&u.z); r.v[4] = f.x; r.v[5] = f.y;
    f = __half22float2(*(__half2*)&u.w); r.v[6] = f.x; r.v[7] = f.y;
    return r;
}
__device__ __forceinline__ void sth8(__half* p, const float* v) {
    uint4 u;
    *(__half2*)&u.x = __floats2half2_rn(v[0], v[1]);
    *(__half2*)&u.y = __floats2half2_rn(v[2], v[3]);
    *(__half2*)&u.z = __floats2half2_rn(v[4], v[5]);
    *(__half2*)&u.w = __floats2half2_rn(v[6], v[7]);
    *(uint4*)p = u;
}

// ---------------------------------------------------------------------------
// tf32 helpers
// ---------------------------------------------------------------------------
__device__ __forceinline__ uint32_t f2tf32(float v) {
    uint32_t r;
    asm("cvt.rna.tf32.f32 %0, %1;" : "=r"(r) : "f"(v));
    return r;
}
__device__ __forceinline__ int kpos8(int k) {   // k in [0,32)
    return (k >> 3) * 8 + (k & 3) * 2 + ((k >> 2) & 1);
}

// ---------------------------------------------------------------------------
// Combined prep kernel: blocks 0-5 build tf32-interleaved Weff (wprep);
// blocks 6.. zero cnt; block 6 also detects edge_index dtype and zeroes acc.
// ---------------------------------------------------------------------------
__global__ __launch_bounds__(1024) void prep_kernel(
    const float* Wg0, const float* Wa0, const float* Wg1, const float* Wa1,
    const float* Wg2, const float* Wa2, float* wout,
    const void* ei, int* cnt, float* acc)
{
    int b = blockIdx.x;
    if (b < 6) {
        const float* W; bool add;
        switch (b) {
            case 0: W = Wg0; add = false; break;
            case 1: W = Wa0; add = false; break;
            case 2: W = Wg1; add = true;  break;
            case 3: W = Wa1; add = false; break;
            case 4: W = Wg2; add = true;  break;
            default: W = Wa2; add = false; break;
        }
        for (int i = threadIdx.x; i < 128 * 128; i += blockDim.x) {
            int n = i & 127, k = i >> 7;
            float v = W[(size_t)k * 128 + n];
            if (add) v += W[(size_t)(k + 128) * 128 + n];
            int ck = k >> 5, kp = kpos8(k & 31);
            wout[(((size_t)(b * 4 + ck) * 128 + n) * 32) + kp] = __uint_as_float(f2tf32(v));
        }
        return;
    }
    int vb = b - 6;
    int i = vb * 1024 + threadIdx.x;
    if (i < NNODES) cnt[i] = 0;
    if (vb == 0) {
        if (threadIdx.x < HDIM) acc[threadIdx.x] = 0.0f;
        __shared__ int ok;
        if (threadIdx.x == 0) ok = 1;
        __syncthreads();
        const long long* p = (const long long*)ei;
        long long v = p[threadIdx.x];      // 1024 samples
        if (v < 0 || v >= NNODES) atomicAnd(&ok, 0);
        __syncthreads();
        if (threadIdx.x == 0) g_is64 = ok;
    }
}

__global__ void cnt_acc_kernel(const void* ei, int* cnt) {
    int e = blockIdx.x * blockDim.x + threadIdx.x;
    if (e >= NEDGES) return;
    int r = g_is64 ? (int)((const long long*)ei)[e] : ((const int*)ei)[e];
    atomicAdd(&cnt[r], 1);
}

// Phase 1: per-block (1024) exclusive scan of deg = cnt+1; block totals.
__global__ __launch_bounds__(1024) void scan1_kernel(
    const int* __restrict__ cnt, int* __restrict__ excl, int* __restrict__ bsum)
{
    __shared__ int wsum[32];
    int t = threadIdx.x;
    int i = blockIdx.x * 1024 + t;
    int lane = t & 31, w = t >> 5;
    int v = (i < NNODES) ? (cnt[i] + 1) : 0;    // +1 = appended self loop
    int s = v;
#pragma unroll
    for (int d = 1; d < 32; d <<= 1) {
        int u = __shfl_up_sync(0xffffffffu, s, d);
        if (lane >= d) s += u;
    }
    if (lane == 31) wsum[w] = s;
    __syncthreads();
    if (w == 0) {
        int ws = wsum[lane];
#pragma unroll
        for (int d = 1; d < 32; d <<= 1) {
            int u = __shfl_up_sync(0xffffffffu, ws, d);
            if (lane >= d) ws += u;
        }
        wsum[lane] = ws;
    }
    __syncthreads();
    int incl = s + (w ? wsum[w - 1] : 0);
    if (i < NNODES) excl[i] = incl - v;
    if (t == 0) bsum[blockIdx.x] = wsum[31];
}

// Phase 2+3 merged: each block prefix-sums bsum locally, finalizes offsets.
__global__ __launch_bounds__(1024) void scan3_kernel(
    const int* __restrict__ cnt, const int* __restrict__ bsum,
    int* __restrict__ offs, int* __restrict__ cur, float* __restrict__ dinv)
{
    __shared__ int base;
    if (threadIdx.x == 0) {
        int run = 0;
        for (int b = 0; b < (int)blockIdx.x; b++) run += bsum[b];
        base = run;
    }
    __syncthreads();
    int i = blockIdx.x * 1024 + threadIdx.x;
    if (i < NNODES) {
        int off = offs[i] + base;
        offs[i] = off;
        cur[i]  = off;
        dinv[i] = rsqrtf((float)(cnt[i] + 1));
    }
    if (i == 0) offs[NNODES] = ETOT;
}

__global__ void csr_scatter_kernel(const void* ei, int* cur, int* csr) {
    int e = blockIdx.x * blockDim.x + threadIdx.x;
    if (e >= ETOT) return;
    int r, c, invalid = 0;
    if (e < NEDGES) {
        if (g_is64) {
            const long long* p = (const long long*)ei;
            r = (int)p[e]; c = (int)p[NEDGES + e];
        } else {
            const int* p = (const int*)ei;
            r = p[e]; c = p[NEDGES + e];
        }
        if (r == c) invalid = (int)0x80000000;  // masked for GAT, kept for GCN
    } else {
        r = c = e - NEDGES;
    }
    int pos = atomicAdd(&cur[r], 1);
    csr[pos] = c | invalid;
}

// ---------------------------------------------------------------------------
// tf32 tensor-core GEMM: C[M,128] = A[M,128] @ Weff[128,128] (+bias|rowscale).
// 256 threads (8 warps, 2 along M x 4 along N), warp tile 64x32.
// SCALE: multiply each output row by dinv[row] (folds GCN symmetric norm).
// ---------------------------------------------------------------------------
#define KS_STRIDE 40

__device__ __forceinline__ void mma_tf32(float4& c, uint32_t a0, uint32_t a1,
                                         uint32_t a2, uint32_t a3,
                                         uint32_t b0, uint32_t b1) {
    asm volatile(
        "mma.sync.aligned.m16n8k8.row.col.f32.tf32.tf32.f32 "
        "{%0,%1,%2,%3}, {%4,%5,%6,%7}, {%8,%9}, {%0,%1,%2,%3};"
        : "+f"(c.x), "+f"(c.y), "+f"(c.z), "+f"(c.w)
        : "r"(a0), "r"(a1), "r"(a2), "r"(a3), "r"(b0), "r"(b1));
}

template<bool AHALF, bool BIAS, bool SCALE>
__global__ __launch_bounds__(256) void mm_tf32_k128(
    const void* __restrict__ Av, const float* __restrict__ wprep, int mat,
    const float* __restrict__ bias, const float* __restrict__ rs,
    __half* __restrict__ C, int M)
{
    __shared__ float Wp[128 * KS_STRIDE];   // [n=128][kpos 0..31]
    __shared__ float Ap[128 * KS_STRIDE];   // [m=128][kpos 0..31]

    const int t    = threadIdx.x;
    const int warp = t >> 5;
    const int lane = t & 31;
    const int gid  = lane >> 2;             // 0..7
    const int tg   = lane & 3;              // 0..3
    const int wm   = warp & 1;              // 2 warps along M (64 rows each)
    const int wn   = warp >> 1;             // 4 warps along N (32 cols each)
    const int m0   = blockIdx.x * 128;

    float4 c[4][4];
#pragma unroll
    for (int i = 0; i < 4; i++)
#pragma unroll
        for (int j = 0; j < 4; j++) c[i][j] = make_float4(0.f, 0.f, 0.f, 0.f);

    for (int ck = 0; ck < 4; ck++) {
        __syncthreads();
        // Stage W chunk: pre-interleaved, pure float4 copies (4 iters)
        const float* wsrc = wprep + ((size_t)(mat * 4 + ck) * 128) * 32;
        for (int i = t; i < 1024; i += 256) {
            int n   = i >> 3;
            int kp4 = (i & 7) << 2;
            *(float4*)&Wp[(size_t)n * KS_STRIDE + kp4] =
                *(const float4*)&wsrc[(size_t)n * 32 + kp4];
        }
        // Stage A chunk: 512 groups of 8 consecutive k (2 iters)
        for (int i = t; i < 512; i += 256) {
            int m = i >> 2;                  // 0..127
            int g = i & 3;                   // 8-k group
            float va[8];
            if (AHALF) {
                F8 v = {};
                if (m0 + m < M)
                    v = ldh8((const __half*)Av + (size_t)(m0 + m) * 128 + ck * 32 + g * 8);
#pragma unroll
                for (int j = 0; j < 8; j++) va[j] = v.v[j];  // fp16 exact in tf32
            } else {
                float4 v0 = make_float4(0.f,0.f,0.f,0.f), v1 = v0;
                if (m0 + m < M) {
                    const float* ap = (const float*)Av + (size_t)(m0 + m) * 128 + ck * 32 + g * 8;
                    v0 = *(const float4*)ap;
                    v1 = *(const float4*)(ap + 4);
                }
                va[0] = __uint_as_float(f2tf32(v0.x)); va[1] = __uint_as_float(f2tf32(v0.y));
                va[2] = __uint_as_float(f2tf32(v0.z)); va[3] = __uint_as_float(f2tf32(v0.w));
                va[4] = __uint_as_float(f2tf32(v1.x)); va[5] = __uint_as_float(f2tf32(v1.y));
                va[6] = __uint_as_float(f2tf32(v1.z)); va[7] = __uint_as_float(f2tf32(v1.w));
            }
            float* ap = &Ap[(size_t)m * KS_STRIDE + g * 8];
#pragma unroll
            for (int j = 0; j < 4; j++)      // pair (k, k+4) -> words (2j, 2j+1)
                *(float2*)&ap[j * 2] = make_float2(va[j], va[j + 4]);
        }
        __syncthreads();

#pragma unroll
        for (int ks = 0; ks < 4; ks++) {
            const int kb = ks * 8 + tg * 2;
            uint32_t b0[4], b1[4];
#pragma unroll
            for (int nt = 0; nt < 4; nt++) {
                int col = wn * 32 + nt * 8 + gid;
                float2 b = *(const float2*)&Wp[(size_t)col * KS_STRIDE + kb];
                b0[nt] = __float_as_uint(b.x);
                b1[nt] = __float_as_uint(b.y);
            }
#pragma unroll
            for (int mt = 0; mt < 4; mt++) {
                int row = wm * 64 + mt * 16 + gid;
                float2 a02 = *(const float2*)&Ap[(size_t)row * KS_STRIDE + kb];
                float2 a13 = *(const float2*)&Ap[(size_t)(row + 8) * KS_STRIDE + kb];
                uint32_t a0 = __float_as_uint(a02.x);
                uint32_t a2 = __float_as_uint(a02.y);
                uint32_t a1 = __float_as_uint(a13.x);
                uint32_t a3 = __float_as_uint(a13.y);
#pragma unroll
                for (int nt = 0; nt < 4; nt++)
                    mma_tf32(c[mt][nt], a0, a1, a2, a3, b0[nt], b1[nt]);
            }
        }
    }

    // Epilogue: optional per-row scale (GCN norm fold) or bias; fp16 output
#pragma unroll
    for (int mt = 0; mt < 4; mt++) {
        int r0 = m0 + wm * 64 + mt * 16 + gid;
        float s0 = 1.f, s1 = 1.f;
        if (SCALE) {
            if (r0 < M)     s0 = __ldg(&rs[r0]);
            if (r0 + 8 < M) s1 = __ldg(&rs[r0 + 8]);
        }
#pragma unroll
        for (int nt = 0; nt < 4; nt++) {
            int col = wn * 32 + nt * 8 + tg * 2;
            float bx = 0.f, by = 0.f;
            if (BIAS) { bx = __ldg(&bias[col]); by = __ldg(&bias[col + 1]); }
            if (r0 < M)
                *(__half2*)&C[(size_t)r0 * 128 + col] =
                    __floats2half2_rn(c[mt][nt].x * s0 + bx, c[mt][nt].y * s0 + by);
            if (r0 + 8 < M)
                *(__half2*)&C[(size_t)(r0 + 8) * 128 + col] =
                    __floats2half2_rn(c[mt][nt].z * s1 + bx, c[mt][nt].w * s1 + by);
        }
    }
}

// ---------------------------------------------------------------------------
// GCN gather: 16 lanes per node (2 nodes/warp). Input rows PRE-SCALED by
// dinv[c] (GEMM epilogue): pure sum of neighbor rows, unroll-4 for loop.
// out = relu(dinv_r * sum + bias).
// ---------------------------------------------------------------------------
__global__ __launch_bounds__(256) void gcn_gather_kernel(
    const __half* __restrict__ xw, const int* __restrict__ offs,
    const int* __restrict__ csr, const float* __restrict__ dinv,
    const float* __restrict__ bias, __half* __restrict__ out)
{
    int node = (blockIdx.x * 256 + threadIdx.x) >> 4;
    int co   = (threadIdx.x & 15) * 8;
    if (node >= NNODES) return;
    int s = __ldg(&offs[node]);
    int e = __ldg(&offs[node + 1]);
    float dr = __ldg(&dinv[node]);

    float a0[8] = {0,0,0,0,0,0,0,0}, a1[8] = {0,0,0,0,0,0,0,0};
    int p = s;
    for (; p + 4 <= e; p += 4) {
        int c0 = __ldg(&csr[p + 0]) & 0x7fffffff;
        int c1 = __ldg(&csr[p + 1]) & 0x7fffffff;
        int c2 = __ldg(&csr[p + 2]) & 0x7fffffff;
        int c3 = __ldg(&csr[p + 3]) & 0x7fffffff;
        F8 v0 = ldh8(xw + (size_t)c0 * 128 + co);
        F8 v1 = ldh8(xw + (size_t)c1 * 128 + co);
        F8 v2 = ldh8(xw + (size_t)c2 * 128 + co);
        F8 v3 = ldh8(xw + (size_t)c3 * 128 + co);
#pragma unroll
        for (int j = 0; j < 8; j++) {
            a0[j] += v0.v[j] + v2.v[j];
            a1[j] += v1.v[j] + v3.v[j];
        }
    }
    for (; p < e; p++) {
        int c0 = __ldg(&csr[p]) & 0x7fffffff;
        F8 v0 = ldh8(xw + (size_t)c0 * 128 + co);
#pragma unroll
        for (int j = 0; j < 8; j++) a0[j] += v0.v[j];
    }
    float4 b0 = *(const float4*)&bias[co];
    float4 b1 = *(const float4*)&bias[co + 4];
    float bb[8] = {b0.x, b0.y, b0.z, b0.w, b1.x, b1.y, b1.z, b1.w};
    float r[8];
#pragma unroll
    for (int j = 0; j < 8; j++)
        r[j] = fmaxf(fmaf(a0[j] + a1[j], dr, bb[j]), 0.0f);
    sth8(out + (size_t)node * 128 + co, r);
}

// ---------------------------------------------------------------------------
// GAT gather: 16 lanes per node (2 nodes/warp), group-mask shfl reduce,
// no-max softmax (logits bounded ~+-25, fp32 exp safe). Unroll-4 for loop.
// LAST variant: skip feature write; block-reduce pooled column sums and
// atomicAdd into g_acc (128 distinct addresses — parallel, cheap).
// ---------------------------------------------------------------------------
template<bool LAST>
__global__ __launch_bounds__(256) void gat_gather_kernel(
    const __half* __restrict__ h, const int* __restrict__ offs,
    const int* __restrict__ csr, __half* __restrict__ out,
    float* __restrict__ acc)
{
    int node = (blockIdx.x * 256 + threadIdx.x) >> 4;
    int co   = (threadIdx.x & 15) * 8;
    const unsigned gmask = 0xFFFFu << (threadIdx.x & 16);   // this 16-lane group
    if (node >= NNODES) return;      // never taken (grid exact)
    int s = __ldg(&offs[node]);
    int e = __ldg(&offs[node + 1]);

    F8 hr = ldh8(h + (size_t)node * 128 + co);

    float den = 0.0f;
    float a0[8] = {0,0,0,0,0,0,0,0}, a1[8] = {0,0,0,0,0,0,0,0};

    int p = s;
    for (; p + 4 <= e; p += 4) {
        int r0 = __ldg(&csr[p + 0]);
        int r1 = __ldg(&csr[p + 1]);
        int r2 = __ldg(&csr[p + 2]);
        int r3 = __ldg(&csr[p + 3]);
        F8 h0 = ldh8(h + (size_t)(r0 & 0x7fffffff) * 128 + co);
        F8 h1 = ldh8(h + (size_t)(r1 & 0x7fffffff) * 128 + co);
        F8 h2 = ldh8(h + (size_t)(r2 & 0x7fffffff) * 128 + co);
        F8 h3 = ldh8(h + (size_t)(r3 & 0x7fffffff) * 128 + co);
        float t0 = 0.f, t1 = 0.f, t2 = 0.f, t3 = 0.f;
#pragma unroll
        for (int j = 0; j < 8; j++) {
            t0 = fmaf(h0.v[j], hr.v[j], t0);
            t1 = fmaf(h1.v[j], hr.v[j], t1);
            t2 = fmaf(h2.v[j], hr.v[j], t2);
            t3 = fmaf(h3.v[j], hr.v[j], t3);
        }
#pragma unroll
        for (int sh = 8; sh; sh >>= 1) {
            t0 += __shfl_xor_sync(gmask, t0, sh);
            t1 += __shfl_xor_sync(gmask, t1, sh);
            t2 += __shfl_xor_sync(gmask, t2, sh);
            t3 += __shfl_xor_sync(gmask, t3, sh);
        }
        float w0 = (r0 >= 0) ? __expf((t0 >= 0.f) ? t0 : 0.2f * t0) : 0.f;
        float w1 = (r1 >= 0) ? __expf((t1 >= 0.f) ? t1 : 0.2f * t1) : 0.f;
        float w2 = (r2 >= 0) ? __expf((t2 >= 0.f) ? t2 : 0.2f * t2) : 0.f;
        float w3 = (r3 >= 0) ? __expf((t3 >= 0.f) ? t3 : 0.2f * t3) : 0.f;
        den += (w0 + w1) + (w2 + w3);
#pragma unroll
        for (int j = 0; j < 8; j++) {
            a0[j] = fmaf(h0.v[j], w0, fmaf(h2.v[j], w2, a0[j]));
            a1[j] = fmaf(h1.v[j], w1, fmaf(h3.v[j], w3, a1[j]));
        }
    }
    for (; p < e; p++) {
        int r0 = __ldg(&csr[p]);
        F8 h0 = ldh8(h + (size_t)(r0 & 0x7fffffff) * 128 + co);
        float t0 = 0.f;
#pragma unroll
        for (int j = 0; j < 8; j++) t0 = fmaf(h0.v[j], hr.v[j], t0);
#pragma unroll
        for (int sh = 8; sh; sh >>= 1) t0 += __shfl_xor_sync(gmask, t0, sh);
        float w0 = (r0 >= 0) ? __expf((t0 >= 0.f) ? t0 : 0.2f * t0) : 0.f;
        den += w0;
#pragma unroll
        for (int j = 0; j < 8; j++) a0[j] = fmaf(h0.v[j], w0, a0[j]);
    }

    float inv = 1.0f / fmaxf(den, 1e-16f);   // den >= exp(self-loop) > 0
    float r[8];
#pragma unroll
    for (int j = 0; j < 8; j++) r[j] = (a0[j] + a1[j]) * inv;

    if (!LAST) {
        sth8(out + (size_t)node * 128 + co, r);
    } else {
        // Fused global-mean-pool: block-reduce 16 nodes, atomic into acc.
        __shared__ float sm[16][HDIM];
        int rg = threadIdx.x >> 4;           // node within block
#pragma unroll
        for (int j = 0; j < 8; j++) sm[rg][co + j] = r[j];
        __syncthreads();
        int t = threadIdx.x;
        if (t < HDIM) {
            float tot = 0.f;
#pragma unroll
            for (int g = 0; g < 16; g++) tot += sm[g][t];
            atomicAdd(&acc[t], tot);
        }
    }
}

// ---------------------------------------------------------------------------
// Final writeout: scale pooled sums -> d_out (x2 concat). Trivial.
// ---------------------------------------------------------------------------
__global__ __launch_bounds__(256) void writeout_kernel(
    const float* __restrict__ acc, float* __restrict__ out)
{
    int t = threadIdx.x;                     // 256 threads
    out[t] = __ldcg(&acc[t & 127]) * (1.0f / (float)NNODES);
}

// ---------------------------------------------------------------------------
// Launch
// ---------------------------------------------------------------------------
extern "C" void kernel_launch(void* const* d_in, const int* in_sizes, int n_in,
                              void* d_out, int out_size)
{
    const float* x  = (const float*)d_in[0];
    const void*  ei = d_in[1];
    const float* Wg[3] = {(const float*)d_in[2], (const float*)d_in[6],  (const float*)d_in[10]};
    const float* bg[3] = {(const float*)d_in[3], (const float*)d_in[7],  (const float*)d_in[11]};
    const float* Wa[3] = {(const float*)d_in[4], (const float*)d_in[8],  (const float*)d_in[12]};
    const float* ba[3] = {(const float*)d_in[5], (const float*)d_in[9],  (const float*)d_in[13]};

    __half *h0, *h1;
    float *dinv, *acc, *wprep;
    int *csr, *cnt, *offs, *cur, *bsum;
    cudaGetSymbolAddress((void**)&h0,   g_h0);
    cudaGetSymbolAddress((void**)&h1,   g_h1);
    cudaGetSymbolAddress((void**)&dinv, g_dinv);
    cudaGetSymbolAddress((void**)&acc,  g_acc);
    cudaGetSymbolAddress((void**)&wprep,g_wprep);
    cudaGetSymbolAddress((void**)&csr,  g_csr);
    cudaGetSymbolAddress((void**)&cnt,  g_cnt);
    cudaGetSymbolAddress((void**)&offs, g_offs);
    cudaGetSymbolAddress((void**)&cur,  g_cur);
    cudaGetSymbolAddress((void**)&bsum, g_bsum);

    const int NB_E    = (NEDGES + 255) / 256;
    const int NB_ET   = (ETOT + 255) / 256;
    const int NB_GEMM = (NNODES + 127) / 128;        // 313

    // Combined weight prep + cnt/acc zero + dtype detect
    prep_kernel<<<6 + SCAN_NB, 1024>>>(Wg[0], Wa[0], Wg[1], Wa[1], Wg[2], Wa[2],
                                       wprep, ei, cnt, acc);
    cnt_acc_kernel<<<NB_E, 256>>>(ei, cnt);
    scan1_kernel<<<SCAN_NB, 1024>>>(cnt, offs, bsum);
    scan3_kernel<<<SCAN_NB, 1024>>>(cnt, bsum, offs, cur, dinv);
    csr_scatter_kernel<<<NB_ET, 256>>>(ei, cur, csr);

    for (int l = 0; l < 3; l++) {
        // --- GCN: GEMM(row-scale by dinv) -> sum-gather(+bias+relu) ---
        if (l == 0)
            mm_tf32_k128<false, false, true><<<NB_GEMM, 256>>>(x,  wprep, 0,     nullptr, dinv, h0, NNODES);
        else
            mm_tf32_k128<true,  false, true><<<NB_GEMM, 256>>>(h1, wprep, l * 2, nullptr, dinv, h0, NNODES);
        gcn_gather_kernel<<<GATH_NB, 256>>>(h0, offs, csr, dinv, bg[l], h1);

        // --- GAT: GEMM(+bias) -> fused softmax gather ---
        mm_tf32_k128<true, true, false><<<NB_GEMM, 256>>>(h1, wprep, l * 2 + 1, ba[l], nullptr, h0, NNODES);
        if (l < 2)
            gat_gather_kernel<false><<<GATH_NB, 256>>>(h0, offs, csr, h1, nullptr);
        else
            gat_gather_kernel<true><<<GATH_NB, 256>>>(h0, offs, csr, nullptr, acc);
    }

    // Scale pooled sums -> output
    writeout_kernel<<<1, 256>>>(acc, (float*)d_out);
}